// round 1
// baseline (speedup 1.0000x reference)
#include <cuda_runtime.h>
#include <math.h>

#define N_NODES 20000
#define N_EDGES 150000
#define FEAT    64
#define HEADS   8
#define N_RBF   20
#define HF      512          // HEADS*FEAT
#define NCOLS   1024         // Q(512) | K(512)
#define CUTOFF  5.0f
#define PI_F    3.14159265358979f

// Scratch: per-node Q and K projections, [node][ Q(0..511) | K(512..1023) ]
__device__ float g_QK[(size_t)N_NODES * NCOLS];

// ---------------------------------------------------------------------------
// Kernel 1: fused Q|K projection GEMM.
// C[n, c] = sum_f x_i[n,f] * W[c,f] + b[c],  W = [W_q ; W_k] rows (c = h*64+g)
// BM=128, BN=128, BK=32, 256 threads, 8x8 microtile.
// ---------------------------------------------------------------------------
#define BM 128
#define BN 128
#define BK 32
#define LDP 132   // padded leading dim for transposed tiles (conflict-free)

__global__ __launch_bounds__(256)
void qk_gemm_kernel(const float* __restrict__ x_i,
                    const float* __restrict__ W_q, const float* __restrict__ b_q,
                    const float* __restrict__ W_k, const float* __restrict__ b_k)
{
    __shared__ float A_t[BK][LDP];   // A_t[k][m]
    __shared__ float B_t[BK][LDP];   // B_t[k][n]

    const int tid  = threadIdx.x;
    const int row0 = blockIdx.x * BM;
    const int col0 = blockIdx.y * BN;

    const float* Bsrc;
    const float* bias_src;
    if (col0 < HF) { Bsrc = W_q + (size_t)col0 * FEAT;        bias_src = b_q + col0; }
    else           { Bsrc = W_k + (size_t)(col0 - HF) * FEAT; bias_src = b_k + (col0 - HF); }

    const int tx = tid & 15;     // 0..15 -> col group
    const int ty = tid >> 4;     // 0..15 -> row group

    float acc[8][8];
    #pragma unroll
    for (int i = 0; i < 8; i++)
        #pragma unroll
        for (int j = 0; j < 8; j++) acc[i][j] = 0.f;

    for (int kk = 0; kk < FEAT; kk += BK) {
        // Fill tiles: 128 rows x 32 k = 1024 float4 total, 4 per thread.
        #pragma unroll
        for (int r = 0; r < 4; r++) {
            int f  = tid + 256 * r;      // 0..1023
            int ml = f >> 3;             // local row 0..127
            int kg = f & 7;              // float4 group within BK
            int m  = row0 + ml;
            float4 va = make_float4(0.f, 0.f, 0.f, 0.f);
            if (m < N_NODES)
                va = *(const float4*)(x_i + (size_t)m * FEAT + kk + kg * 4);
            A_t[kg * 4 + 0][ml] = va.x;
            A_t[kg * 4 + 1][ml] = va.y;
            A_t[kg * 4 + 2][ml] = va.z;
            A_t[kg * 4 + 3][ml] = va.w;
            float4 vb = *(const float4*)(Bsrc + (size_t)ml * FEAT + kk + kg * 4);
            B_t[kg * 4 + 0][ml] = vb.x;
            B_t[kg * 4 + 1][ml] = vb.y;
            B_t[kg * 4 + 2][ml] = vb.z;
            B_t[kg * 4 + 3][ml] = vb.w;
        }
        __syncthreads();

        #pragma unroll
        for (int k = 0; k < BK; k++) {
            float a[8], b[8];
            *(float4*)(a)     = *(const float4*)&A_t[k][ty * 8];
            *(float4*)(a + 4) = *(const float4*)&A_t[k][ty * 8 + 4];
            *(float4*)(b)     = *(const float4*)&B_t[k][tx * 8];
            *(float4*)(b + 4) = *(const float4*)&B_t[k][tx * 8 + 4];
            #pragma unroll
            for (int i = 0; i < 8; i++)
                #pragma unroll
                for (int j = 0; j < 8; j++)
                    acc[i][j] += a[i] * b[j];
        }
        __syncthreads();
    }

    float bias[8];
    #pragma unroll
    for (int j = 0; j < 8; j++) bias[j] = bias_src[tx * 8 + j];

    #pragma unroll
    for (int i = 0; i < 8; i++) {
        int m = row0 + ty * 8 + i;
        if (m < N_NODES) {
            float* dst = &g_QK[(size_t)m * NCOLS + col0 + tx * 8];
            float4 o0, o1;
            o0.x = acc[i][0] + bias[0]; o0.y = acc[i][1] + bias[1];
            o0.z = acc[i][2] + bias[2]; o0.w = acc[i][3] + bias[3];
            o1.x = acc[i][4] + bias[4]; o1.y = acc[i][5] + bias[5];
            o1.z = acc[i][6] + bias[6]; o1.w = acc[i][7] + bias[7];
            *(float4*)(dst)     = o0;
            *(float4*)(dst + 4) = o1;
        }
    }
}

// ---------------------------------------------------------------------------
// Kernel 2: fused edge kernel.
// Thread t owns column hf = t (h = hf/64, f = hf%64). Its W_dk[h,f,0..19]
// stays in registers for all edges. 8 edges per block iteration.
// ---------------------------------------------------------------------------
#define EPB 8            // edges per block iteration
#define NGROUPS ((N_EDGES + EPB - 1) / EPB)

__device__ __forceinline__ float silu_f(float x) {
    return __fdividef(x, 1.f + __expf(-x));
}

__global__ __launch_bounds__(512)
void edge_kernel(const float* __restrict__ dist,
                 const int*   __restrict__ nbrs,
                 const float* __restrict__ W_dk,
                 const float* __restrict__ b_dk,
                 float*       __restrict__ out)
{
    __shared__ float ef_s[EPB][24];     // 20 RBF values, padded row (96B, f4-aligned)
    __shared__ int   idx_s[EPB][2];
    __shared__ float part_s[EPB][16];   // per-warp partial sums

    const int tid  = threadIdx.x;       // == hf
    const int lane = tid & 31;
    const int warp = tid >> 5;

    // Per-thread W_dk row in registers (20 floats = 5 float4, 80B offset is 16B aligned)
    const float4* wp = (const float4*)(W_dk + (size_t)tid * N_RBF);
    const float4 w0 = wp[0], w1 = wp[1], w2 = wp[2], w3 = wp[3], w4 = wp[4];
    const float  bb = b_dk[tid];

    for (int g = blockIdx.x; g < NGROUPS; g += gridDim.x) {
        const int e0 = g * EPB;

        // --- stage 1: RBF features + neighbor indices into shared ---
        if (tid < EPB * N_RBF) {
            int el = tid / N_RBF, r = tid % N_RBF;
            int e = e0 + el;
            float v = 0.f;
            if (e < N_EDGES) {
                float d   = dist[e];
                float env = (d < CUTOFF) ? 0.5f * (cosf(PI_F * d / CUTOFF) + 1.f) : 0.f;
                v = sinf((float)(r + 1) * PI_F * d / CUTOFF) / d * env;
            }
            ef_s[el][r] = v;
        }
        if (tid < EPB * 2) {
            int el = tid >> 1, c = tid & 1;
            int e = e0 + el;
            idx_s[el][c] = (e < N_EDGES) ? nbrs[2 * e + c] : 0;
        }
        __syncthreads();

        // --- stage 2: per-edge d_k + triple-product partial reduction ---
        #pragma unroll
        for (int el = 0; el < EPB; el++) {
            int e = e0 + el;            // uniform across block
            float psum = 0.f;
            if (e < N_EDGES) {
                int ni = idx_s[el][0];
                int nj = idx_s[el][1];
                float q = g_QK[(size_t)ni * NCOLS + tid];
                float k = g_QK[(size_t)nj * NCOLS + HF + tid];
                const float4* efp = (const float4*)&ef_s[el][0];
                float4 e0v = efp[0], e1v = efp[1], e2v = efp[2], e3v = efp[3], e4v = efp[4];
                float s = bb;
                s += e0v.x * w0.x; s += e0v.y * w0.y; s += e0v.z * w0.z; s += e0v.w * w0.w;
                s += e1v.x * w1.x; s += e1v.y * w1.y; s += e1v.z * w1.z; s += e1v.w * w1.w;
                s += e2v.x * w2.x; s += e2v.y * w2.y; s += e2v.z * w2.z; s += e2v.w * w2.w;
                s += e3v.x * w3.x; s += e3v.y * w3.y; s += e3v.z * w3.z; s += e3v.w * w3.w;
                s += e4v.x * w4.x; s += e4v.y * w4.y; s += e4v.z * w4.z; s += e4v.w * w4.w;
                float dk = silu_f(s);
                psum = q * k * dk;
            }
            // warp butterfly reduce (64 f-lanes of a head live in warps 2h, 2h+1)
            #pragma unroll
            for (int o = 16; o > 0; o >>= 1)
                psum += __shfl_xor_sync(0xffffffffu, psum, o);
            if (lane == 0) part_s[el][warp] = psum;
        }
        __syncthreads();

        // --- stage 3: combine warp pairs, silu, write ---
        if (tid < EPB * HEADS) {
            int el = tid >> 3, hh = tid & 7;
            int e = e0 + el;
            if (e < N_EDGES) {
                float s = part_s[el][2 * hh] + part_s[el][2 * hh + 1];
                out[(size_t)e * HEADS + hh] = silu_f(s);
            }
        }
        __syncthreads();
    }
}

// ---------------------------------------------------------------------------
extern "C" void kernel_launch(void* const* d_in, const int* in_sizes, int n_in,
                              void* d_out, int out_size)
{
    const float* dist = (const float*)d_in[0];
    const int*   nbrs = (const int*)  d_in[1];
    const float* x_i  = (const float*)d_in[2];
    const float* W_q  = (const float*)d_in[3];
    const float* b_q  = (const float*)d_in[4];
    const float* W_k  = (const float*)d_in[5];
    const float* b_k  = (const float*)d_in[6];
    const float* W_dk = (const float*)d_in[7];
    const float* b_dk = (const float*)d_in[8];
    float* out = (float*)d_out;

    dim3 g1((N_NODES + BM - 1) / BM, NCOLS / BN);   // 157 x 8
    qk_gemm_kernel<<<g1, 256>>>(x_i, W_q, b_q, W_k, b_k);

    edge_kernel<<<296, 512>>>(dist, nbrs, W_dk, b_dk, out);
}

// round 4
// speedup vs baseline: 1.2779x; 1.2779x over previous
#include <cuda_runtime.h>
#include <math.h>

#define N_NODES 20000
#define N_EDGES 150000
#define FEAT    64
#define HEADS   8
#define N_RBF   20
#define HF      512          // HEADS*FEAT
#define NCOLS   1024         // Q(512) | K(512)
#define CUTOFF  5.0f
#define PI_F    3.14159265358979f

// Scratch: per-node Q and K projections, [node][ Q(0..511) | K(512..1023) ]
__device__ float g_QK[(size_t)N_NODES * NCOLS];

// ---------------------------------------------------------------------------
// Kernel 1: fused Q|K projection GEMM.
// C[n, c] = sum_f x_i[n,f] * W[c,f] + b[c],  W = [W_q ; W_k] rows (c = h*64+g)
// BM=128, BN=128, BK=32, 256 threads, 8x8 microtile.
// ---------------------------------------------------------------------------
#define BM 128
#define BN 128
#define BK 32
#define LDP 132   // padded leading dim for transposed tiles (conflict-free)

__global__ __launch_bounds__(256)
void qk_gemm_kernel(const float* __restrict__ x_i,
                    const float* __restrict__ W_q, const float* __restrict__ b_q,
                    const float* __restrict__ W_k, const float* __restrict__ b_k)
{
    __shared__ float A_t[BK][LDP];   // A_t[k][m]
    __shared__ float B_t[BK][LDP];   // B_t[k][n]

    const int tid  = threadIdx.x;
    const int row0 = blockIdx.x * BM;
    const int col0 = blockIdx.y * BN;

    const float* Bsrc;
    const float* bias_src;
    if (col0 < HF) { Bsrc = W_q + (size_t)col0 * FEAT;        bias_src = b_q + col0; }
    else           { Bsrc = W_k + (size_t)(col0 - HF) * FEAT; bias_src = b_k + (col0 - HF); }

    const int tx = tid & 15;     // 0..15 -> col group
    const int ty = tid >> 4;     // 0..15 -> row group

    float acc[8][8];
    #pragma unroll
    for (int i = 0; i < 8; i++)
        #pragma unroll
        for (int j = 0; j < 8; j++) acc[i][j] = 0.f;

    for (int kk = 0; kk < FEAT; kk += BK) {
        // Fill tiles: 128 rows x 32 k = 1024 float4 total, 4 per thread.
        #pragma unroll
        for (int r = 0; r < 4; r++) {
            int f  = tid + 256 * r;      // 0..1023
            int ml = f >> 3;             // local row 0..127
            int kg = f & 7;              // float4 group within BK
            int m  = row0 + ml;
            float4 va = make_float4(0.f, 0.f, 0.f, 0.f);
            if (m < N_NODES)
                va = *(const float4*)(x_i + (size_t)m * FEAT + kk + kg * 4);
            A_t[kg * 4 + 0][ml] = va.x;
            A_t[kg * 4 + 1][ml] = va.y;
            A_t[kg * 4 + 2][ml] = va.z;
            A_t[kg * 4 + 3][ml] = va.w;
            float4 vb = *(const float4*)(Bsrc + (size_t)ml * FEAT + kk + kg * 4);
            B_t[kg * 4 + 0][ml] = vb.x;
            B_t[kg * 4 + 1][ml] = vb.y;
            B_t[kg * 4 + 2][ml] = vb.z;
            B_t[kg * 4 + 3][ml] = vb.w;
        }
        __syncthreads();

        #pragma unroll
        for (int k = 0; k < BK; k++) {
            float a[8], b[8];
            *(float4*)(a)     = *(const float4*)&A_t[k][ty * 8];
            *(float4*)(a + 4) = *(const float4*)&A_t[k][ty * 8 + 4];
            *(float4*)(b)     = *(const float4*)&B_t[k][tx * 8];
            *(float4*)(b + 4) = *(const float4*)&B_t[k][tx * 8 + 4];
            #pragma unroll
            for (int i = 0; i < 8; i++)
                #pragma unroll
                for (int j = 0; j < 8; j++)
                    acc[i][j] += a[i] * b[j];
        }
        __syncthreads();
    }

    float bias[8];
    #pragma unroll
    for (int j = 0; j < 8; j++) bias[j] = bias_src[tx * 8 + j];

    #pragma unroll
    for (int i = 0; i < 8; i++) {
        int m = row0 + ty * 8 + i;
        if (m < N_NODES) {
            float* dst = &g_QK[(size_t)m * NCOLS + col0 + tx * 8];
            float4 o0, o1;
            o0.x = acc[i][0] + bias[0]; o0.y = acc[i][1] + bias[1];
            o0.z = acc[i][2] + bias[2]; o0.w = acc[i][3] + bias[3];
            o1.x = acc[i][4] + bias[4]; o1.y = acc[i][5] + bias[5];
            o1.z = acc[i][6] + bias[6]; o1.w = acc[i][7] + bias[7];
            *(float4*)(dst)     = o0;
            *(float4*)(dst + 4) = o1;
        }
    }
}

// ---------------------------------------------------------------------------
// Kernel 2: fused edge kernel.
// Thread t owns column hf = t (h = hf/64, f = hf%64). Its W_dk[h,f,0..19]
// stays in registers for all edges. 16 edges per iteration (150000 = 16*9375,
// no tail). Reduction: 3-level butterfly -> 4 partials/warp -> stage-3 sum.
// ---------------------------------------------------------------------------
#define EPB 16                    // edges per block iteration
#define NGROUPS (N_EDGES / EPB)   // 9375, exact
#define GRID2   444               // 148 SMs * 3 CTAs

__device__ __forceinline__ float silu_f(float x) {
    return __fdividef(x, 1.f + __expf(-x));
}

__global__ __launch_bounds__(512, 3)
void edge_kernel(const float* __restrict__ dist,
                 const int*   __restrict__ nbrs,
                 const float* __restrict__ W_dk,
                 const float* __restrict__ b_dk,
                 float*       __restrict__ out)
{
    __shared__ float ef_s[EPB][24];     // 20 RBF values, padded row (96B, f4-aligned)
    __shared__ int2  idx_s[EPB];
    __shared__ float part_s[EPB][64];   // 4 partials per warp x 16 warps

    const int tid  = threadIdx.x;       // == hf
    const int lane = tid & 31;
    const int warp = tid >> 5;
    const int pidx = warp * 4 + (lane >> 3);   // partial slot for this thread's octet

    // Base pointers with the column offset folded in once (saves an IADD in the loop)
    const float* __restrict__ gQ = g_QK + tid;
    const float* __restrict__ gK = g_QK + HF + tid;

    // Per-thread W_dk row in registers (20 floats = 5 float4, 80B offset is 16B aligned)
    const float4* wp = (const float4*)(W_dk + (size_t)tid * N_RBF);
    const float4 w0 = wp[0], w1 = wp[1], w2 = wp[2], w3 = wp[3], w4 = wp[4];
    const float  bb = b_dk[tid];

    for (int g = blockIdx.x; g < NGROUPS; g += GRID2) {
        const int e0 = g * EPB;

        // --- stage 1: RBF features + neighbor indices into shared ---
        if (tid < EPB * N_RBF) {
            int el = tid / N_RBF, r = tid % N_RBF;
            float d   = dist[e0 + el];
            float t   = PI_F * d * (1.0f / CUTOFF);
            float env = (d < CUTOFF) ? 0.5f * (cosf(t) + 1.f) : 0.f;
            ef_s[el][r] = sinf((float)(r + 1) * t) * __fdividef(env, d);
        }
        if (tid < EPB) {
            idx_s[tid] = ((const int2*)nbrs)[e0 + tid];
        }
        __syncthreads();

        // --- stage 2: per-edge d_k + triple-product partial reduction ---
        #pragma unroll 2
        for (int el = 0; el < EPB; el++) {
            int2 nn = idx_s[el];
            float q = gQ[(size_t)nn.x * NCOLS];
            float k = gK[(size_t)nn.y * NCOLS];
            const float4* efp = (const float4*)&ef_s[el][0];
            float4 e0v = efp[0], e1v = efp[1], e2v = efp[2], e3v = efp[3], e4v = efp[4];
            float s = bb;
            s += e0v.x * w0.x; s += e0v.y * w0.y; s += e0v.z * w0.z; s += e0v.w * w0.w;
            s += e1v.x * w1.x; s += e1v.y * w1.y; s += e1v.z * w1.z; s += e1v.w * w1.w;
            s += e2v.x * w2.x; s += e2v.y * w2.y; s += e2v.z * w2.z; s += e2v.w * w2.w;
            s += e3v.x * w3.x; s += e3v.y * w3.y; s += e3v.z * w3.z; s += e3v.w * w3.w;
            s += e4v.x * w4.x; s += e4v.y * w4.y; s += e4v.z * w4.z; s += e4v.w * w4.w;
            float p = q * k * silu_f(s);
            // 3-level butterfly within octets of 8 lanes
            p += __shfl_xor_sync(0xffffffffu, p, 4);
            p += __shfl_xor_sync(0xffffffffu, p, 2);
            p += __shfl_xor_sync(0xffffffffu, p, 1);
            if ((lane & 7) == 0) part_s[el][pidx] = p;
        }
        __syncthreads();

        // --- stage 3: sum 8 partials per (edge, head), silu, write ---
        if (tid < EPB * HEADS) {
            int el = tid >> 3, hh = tid & 7;
            const float4* pp = (const float4*)&part_s[el][hh * 8];
            float4 p0 = pp[0], p1 = pp[1];
            float s = ((p0.x + p0.y) + (p0.z + p0.w)) + ((p1.x + p1.y) + (p1.z + p1.w));
            out[(size_t)(e0 + el) * HEADS + hh] = silu_f(s);
        }
        __syncthreads();
    }
}

// ---------------------------------------------------------------------------
extern "C" void kernel_launch(void* const* d_in, const int* in_sizes, int n_in,
                              void* d_out, int out_size)
{
    const float* dist = (const float*)d_in[0];
    const int*   nbrs = (const int*)  d_in[1];
    const float* x_i  = (const float*)d_in[2];
    const float* W_q  = (const float*)d_in[3];
    const float* b_q  = (const float*)d_in[4];
    const float* W_k  = (const float*)d_in[5];
    const float* b_k  = (const float*)d_in[6];
    const float* W_dk = (const float*)d_in[7];
    const float* b_dk = (const float*)d_in[8];
    float* out = (float*)d_out;

    dim3 g1((N_NODES + BM - 1) / BM, NCOLS / BN);   // 157 x 8
    qk_gemm_kernel<<<g1, 256>>>(x_i, W_q, b_q, W_k, b_k);

    edge_kernel<<<GRID2, 512>>>(dist, nbrs, W_dk, b_dk, out);
}

// round 5
// speedup vs baseline: 1.2958x; 1.0140x over previous
#include <cuda_runtime.h>
#include <math.h>

#define N_NODES 20000
#define N_EDGES 150000
#define FEAT    64
#define HEADS   8
#define N_RBF   20
#define HF      512          // HEADS*FEAT
#define NCOLS   1024         // Q(512) | K(512)
#define CUTOFF  5.0f
#define PI_F    3.14159265358979f

// Scratch: per-node Q and K projections, [node][ Q(0..511) | K(512..1023) ]
__device__ float g_QK[(size_t)N_NODES * NCOLS];

// ---------------------------------------------------------------------------
// Kernel 1: fused Q|K projection GEMM.
// C[n, c] = sum_f x_i[n,f] * W[c,f] + b[c],  W = [W_q ; W_k] rows (c = h*64+g)
// BM=128, BN=128, BK=32, 256 threads, 8x8 microtile.
// ---------------------------------------------------------------------------
#define BM 128
#define BN 128
#define BK 32
#define LDP 132   // padded leading dim for transposed tiles (conflict-free)

__global__ __launch_bounds__(256)
void qk_gemm_kernel(const float* __restrict__ x_i,
                    const float* __restrict__ W_q, const float* __restrict__ b_q,
                    const float* __restrict__ W_k, const float* __restrict__ b_k)
{
    __shared__ float A_t[BK][LDP];   // A_t[k][m]
    __shared__ float B_t[BK][LDP];   // B_t[k][n]

    const int tid  = threadIdx.x;
    const int row0 = blockIdx.x * BM;
    const int col0 = blockIdx.y * BN;

    const float* Bsrc;
    const float* bias_src;
    if (col0 < HF) { Bsrc = W_q + (size_t)col0 * FEAT;        bias_src = b_q + col0; }
    else           { Bsrc = W_k + (size_t)(col0 - HF) * FEAT; bias_src = b_k + (col0 - HF); }

    const int tx = tid & 15;     // 0..15 -> col group
    const int ty = tid >> 4;     // 0..15 -> row group

    float acc[8][8];
    #pragma unroll
    for (int i = 0; i < 8; i++)
        #pragma unroll
        for (int j = 0; j < 8; j++) acc[i][j] = 0.f;

    for (int kk = 0; kk < FEAT; kk += BK) {
        // Fill tiles: 128 rows x 32 k = 1024 float4 total, 4 per thread.
        #pragma unroll
        for (int r = 0; r < 4; r++) {
            int f  = tid + 256 * r;      // 0..1023
            int ml = f >> 3;             // local row 0..127
            int kg = f & 7;              // float4 group within BK
            int m  = row0 + ml;
            float4 va = make_float4(0.f, 0.f, 0.f, 0.f);
            if (m < N_NODES)
                va = *(const float4*)(x_i + (size_t)m * FEAT + kk + kg * 4);
            A_t[kg * 4 + 0][ml] = va.x;
            A_t[kg * 4 + 1][ml] = va.y;
            A_t[kg * 4 + 2][ml] = va.z;
            A_t[kg * 4 + 3][ml] = va.w;
            float4 vb = *(const float4*)(Bsrc + (size_t)ml * FEAT + kk + kg * 4);
            B_t[kg * 4 + 0][ml] = vb.x;
            B_t[kg * 4 + 1][ml] = vb.y;
            B_t[kg * 4 + 2][ml] = vb.z;
            B_t[kg * 4 + 3][ml] = vb.w;
        }
        __syncthreads();

        #pragma unroll
        for (int k = 0; k < BK; k++) {
            float a[8], b[8];
            *(float4*)(a)     = *(const float4*)&A_t[k][ty * 8];
            *(float4*)(a + 4) = *(const float4*)&A_t[k][ty * 8 + 4];
            *(float4*)(b)     = *(const float4*)&B_t[k][tx * 8];
            *(float4*)(b + 4) = *(const float4*)&B_t[k][tx * 8 + 4];
            #pragma unroll
            for (int i = 0; i < 8; i++)
                #pragma unroll
                for (int j = 0; j < 8; j++)
                    acc[i][j] += a[i] * b[j];
        }
        __syncthreads();
    }

    float bias[8];
    #pragma unroll
    for (int j = 0; j < 8; j++) bias[j] = bias_src[tx * 8 + j];

    #pragma unroll
    for (int i = 0; i < 8; i++) {
        int m = row0 + ty * 8 + i;
        if (m < N_NODES) {
            float* dst = &g_QK[(size_t)m * NCOLS + col0 + tx * 8];
            float4 o0, o1;
            o0.x = acc[i][0] + bias[0]; o0.y = acc[i][1] + bias[1];
            o0.z = acc[i][2] + bias[2]; o0.w = acc[i][3] + bias[3];
            o1.x = acc[i][4] + bias[4]; o1.y = acc[i][5] + bias[5];
            o1.z = acc[i][6] + bias[6]; o1.w = acc[i][7] + bias[7];
            *(float4*)(dst)     = o0;
            *(float4*)(dst + 4) = o1;
        }
    }
}

// ---------------------------------------------------------------------------
// Kernel 2: fused edge kernel.
// Thread t owns column hf = t. Its W_dk[h,f,0..19] stays in registers,
// reinterpreted as 10 packed f32x2 pairs along the RBF axis; the 20-FMA dot
// becomes 10 x fma.rn.f32x2 into 2 interleaved packed accumulators.
// 16 edges per iteration (150000 = 16*9375, no tail).
// ---------------------------------------------------------------------------
#define EPB 16                    // edges per block iteration
#define NGROUPS (N_EDGES / EPB)   // 9375, exact
#define GRID2   444               // 148 SMs * 3 CTAs

__device__ __forceinline__ float silu_f(float x) {
    return __fdividef(x, 1.f + __expf(-x));
}

__device__ __forceinline__ unsigned long long ffma2(unsigned long long a,
                                                    unsigned long long b,
                                                    unsigned long long c) {
    unsigned long long d;
    asm("fma.rn.f32x2 %0, %1, %2, %3;" : "=l"(d) : "l"(a), "l"(b), "l"(c));
    return d;
}

__device__ __forceinline__ unsigned long long pack2(float lo, float hi) {
    unsigned long long r;
    asm("mov.b64 %0, {%1, %2};" : "=l"(r) : "f"(lo), "f"(hi));
    return r;
}

__device__ __forceinline__ float2 unpack2(unsigned long long v) {
    float2 r;
    asm("mov.b64 {%0, %1}, %2;" : "=f"(r.x), "=f"(r.y) : "l"(v));
    return r;
}

__global__ __launch_bounds__(512, 3)
void edge_kernel(const float* __restrict__ dist,
                 const int*   __restrict__ nbrs,
                 const float* __restrict__ W_dk,
                 const float* __restrict__ b_dk,
                 float*       __restrict__ out)
{
    __shared__ alignas(16) float ef_s[EPB][24];   // 20 RBF values, padded row
    __shared__ int2  idx_s[EPB];
    __shared__ float part_s[EPB][64];   // 4 partials per warp x 16 warps

    const int tid  = threadIdx.x;       // == hf
    const int lane = tid & 31;
    const int warp = tid >> 5;
    const int pidx = warp * 4 + (lane >> 3);   // partial slot for this thread's octet

    // Base pointers with the column offset folded in once
    const float* __restrict__ gQ = g_QK + tid;
    const float* __restrict__ gK = g_QK + HF + tid;

    // W_dk row (20 floats, 16B-aligned since 80 = 5*16) as 10 packed f32x2 pairs
    const ulonglong2* wp = (const ulonglong2*)(W_dk + (size_t)tid * N_RBF);
    const ulonglong2 wv0 = wp[0], wv1 = wp[1], wv2 = wp[2], wv3 = wp[3], wv4 = wp[4];
    const float bb = b_dk[tid];
    const unsigned long long accA0 = pack2(bb, 0.f);   // bias seeds chain A
    const unsigned long long accB0 = pack2(0.f, 0.f);

    for (int g = blockIdx.x; g < NGROUPS; g += GRID2) {
        const int e0 = g * EPB;

        // --- stage 1: RBF features + neighbor indices into shared ---
        if (tid < EPB * N_RBF) {
            int el = tid / N_RBF, r = tid % N_RBF;
            float d   = dist[e0 + el];
            float t   = PI_F * d * (1.0f / CUTOFF);
            float env = (d < CUTOFF) ? 0.5f * (__cosf(t) + 1.f) : 0.f;
            ef_s[el][r] = __sinf((float)(r + 1) * t) * __fdividef(env, d);
        }
        if (tid < EPB) {
            idx_s[tid] = ((const int2*)nbrs)[e0 + tid];
        }
        __syncthreads();

        // --- stage 2: per-edge d_k + triple-product partial reduction ---
        #pragma unroll 2
        for (int el = 0; el < EPB; el++) {
            int2 nn = idx_s[el];
            float q = gQ[(size_t)nn.x * NCOLS];
            float k = gK[(size_t)nn.y * NCOLS];
            const ulonglong2* efp = (const ulonglong2*)&ef_s[el][0];
            ulonglong2 ev0 = efp[0], ev1 = efp[1], ev2 = efp[2], ev3 = efp[3], ev4 = efp[4];
            unsigned long long accA = accA0, accB = accB0;
            accA = ffma2(ev0.x, wv0.x, accA);
            accB = ffma2(ev0.y, wv0.y, accB);
            accA = ffma2(ev1.x, wv1.x, accA);
            accB = ffma2(ev1.y, wv1.y, accB);
            accA = ffma2(ev2.x, wv2.x, accA);
            accB = ffma2(ev2.y, wv2.y, accB);
            accA = ffma2(ev3.x, wv3.x, accA);
            accB = ffma2(ev3.y, wv3.y, accB);
            accA = ffma2(ev4.x, wv4.x, accA);
            accB = ffma2(ev4.y, wv4.y, accB);
            float2 fa = unpack2(accA);
            float2 fb = unpack2(accB);
            float s = (fa.x + fa.y) + (fb.x + fb.y);
            float p = q * k * silu_f(s);
            // 3-level butterfly within octets of 8 lanes
            p += __shfl_xor_sync(0xffffffffu, p, 4);
            p += __shfl_xor_sync(0xffffffffu, p, 2);
            p += __shfl_xor_sync(0xffffffffu, p, 1);
            if ((lane & 7) == 0) part_s[el][pidx] = p;
        }
        __syncthreads();

        // --- stage 3: sum 8 partials per (edge, head), silu, write ---
        if (tid < EPB * HEADS) {
            int el = tid >> 3, hh = tid & 7;
            const float4* pp = (const float4*)&part_s[el][hh * 8];
            float4 p0 = pp[0], p1 = pp[1];
            float s = ((p0.x + p0.y) + (p0.z + p0.w)) + ((p1.x + p1.y) + (p1.z + p1.w));
            out[(size_t)(e0 + el) * HEADS + hh] = silu_f(s);
        }
        __syncthreads();
    }
}

// ---------------------------------------------------------------------------
extern "C" void kernel_launch(void* const* d_in, const int* in_sizes, int n_in,
                              void* d_out, int out_size)
{
    const float* dist = (const float*)d_in[0];
    const int*   nbrs = (const int*)  d_in[1];
    const float* x_i  = (const float*)d_in[2];
    const float* W_q  = (const float*)d_in[3];
    const float* b_q  = (const float*)d_in[4];
    const float* W_k  = (const float*)d_in[5];
    const float* b_k  = (const float*)d_in[6];
    const float* W_dk = (const float*)d_in[7];
    const float* b_dk = (const float*)d_in[8];
    float* out = (float*)d_out;

    dim3 g1((N_NODES + BM - 1) / BM, NCOLS / BN);   // 157 x 8
    qk_gemm_kernel<<<g1, 256>>>(x_i, W_q, b_q, W_k, b_k);

    edge_kernel<<<GRID2, 512>>>(dist, nbrs, W_dk, b_dk, out);
}

// round 6
// speedup vs baseline: 1.3611x; 1.0504x over previous
#include <cuda_runtime.h>
#include <math.h>

#define N_NODES 20000
#define N_EDGES 150000
#define FEAT    64
#define HEADS   8
#define N_RBF   20
#define HF      512          // HEADS*FEAT
#define NCOLS   1024         // Q(512) | K(512)
#define CUTOFF  5.0f
#define PI_F    3.14159265358979f

// Scratch: per-node Q and K projections, [node][ Q(0..511) | K(512..1023) ]
__device__ float g_QK[(size_t)N_NODES * NCOLS];

// ---------------------------------------------------------------------------
// Kernel 1: fused Q|K projection GEMM (unchanged).
// ---------------------------------------------------------------------------
#define BM 128
#define BN 128
#define BK 32
#define LDP 132   // padded leading dim for transposed tiles (conflict-free)

__global__ __launch_bounds__(256)
void qk_gemm_kernel(const float* __restrict__ x_i,
                    const float* __restrict__ W_q, const float* __restrict__ b_q,
                    const float* __restrict__ W_k, const float* __restrict__ b_k)
{
    __shared__ float A_t[BK][LDP];   // A_t[k][m]
    __shared__ float B_t[BK][LDP];   // B_t[k][n]

    const int tid  = threadIdx.x;
    const int row0 = blockIdx.x * BM;
    const int col0 = blockIdx.y * BN;

    const float* Bsrc;
    const float* bias_src;
    if (col0 < HF) { Bsrc = W_q + (size_t)col0 * FEAT;        bias_src = b_q + col0; }
    else           { Bsrc = W_k + (size_t)(col0 - HF) * FEAT; bias_src = b_k + (col0 - HF); }

    const int tx = tid & 15;     // 0..15 -> col group
    const int ty = tid >> 4;     // 0..15 -> row group

    float acc[8][8];
    #pragma unroll
    for (int i = 0; i < 8; i++)
        #pragma unroll
        for (int j = 0; j < 8; j++) acc[i][j] = 0.f;

    for (int kk = 0; kk < FEAT; kk += BK) {
        #pragma unroll
        for (int r = 0; r < 4; r++) {
            int f  = tid + 256 * r;      // 0..1023
            int ml = f >> 3;             // local row 0..127
            int kg = f & 7;              // float4 group within BK
            int m  = row0 + ml;
            float4 va = make_float4(0.f, 0.f, 0.f, 0.f);
            if (m < N_NODES)
                va = *(const float4*)(x_i + (size_t)m * FEAT + kk + kg * 4);
            A_t[kg * 4 + 0][ml] = va.x;
            A_t[kg * 4 + 1][ml] = va.y;
            A_t[kg * 4 + 2][ml] = va.z;
            A_t[kg * 4 + 3][ml] = va.w;
            float4 vb = *(const float4*)(Bsrc + (size_t)ml * FEAT + kk + kg * 4);
            B_t[kg * 4 + 0][ml] = vb.x;
            B_t[kg * 4 + 1][ml] = vb.y;
            B_t[kg * 4 + 2][ml] = vb.z;
            B_t[kg * 4 + 3][ml] = vb.w;
        }
        __syncthreads();

        #pragma unroll
        for (int k = 0; k < BK; k++) {
            float a[8], b[8];
            *(float4*)(a)     = *(const float4*)&A_t[k][ty * 8];
            *(float4*)(a + 4) = *(const float4*)&A_t[k][ty * 8 + 4];
            *(float4*)(b)     = *(const float4*)&B_t[k][tx * 8];
            *(float4*)(b + 4) = *(const float4*)&B_t[k][tx * 8 + 4];
            #pragma unroll
            for (int i = 0; i < 8; i++)
                #pragma unroll
                for (int j = 0; j < 8; j++)
                    acc[i][j] += a[i] * b[j];
        }
        __syncthreads();
    }

    float bias[8];
    #pragma unroll
    for (int j = 0; j < 8; j++) bias[j] = bias_src[tx * 8 + j];

    #pragma unroll
    for (int i = 0; i < 8; i++) {
        int m = row0 + ty * 8 + i;
        if (m < N_NODES) {
            float* dst = &g_QK[(size_t)m * NCOLS + col0 + tx * 8];
            float4 o0, o1;
            o0.x = acc[i][0] + bias[0]; o0.y = acc[i][1] + bias[1];
            o0.z = acc[i][2] + bias[2]; o0.w = acc[i][3] + bias[3];
            o1.x = acc[i][4] + bias[4]; o1.y = acc[i][5] + bias[5];
            o1.z = acc[i][6] + bias[6]; o1.w = acc[i][7] + bias[7];
            *(float4*)(dst)     = o0;
            *(float4*)(dst + 4) = o1;
        }
    }
}

// ---------------------------------------------------------------------------
// Kernel 2: fused edge kernel, 256 threads, warp == head, 2 cols/thread.
// Double-buffered ef_s; one barrier per 16 edges. W_dk rows for both columns
// in registers as r-packed f32x2 pairs (20 FFMA2/edge/thread).
// ---------------------------------------------------------------------------
#define EPB 16                    // edges per block iteration
#define NGROUPS (N_EDGES / EPB)   // 9375, exact
#define GRID2   444               // 148 SMs * 3 CTAs
#define TPB2    256

__device__ __forceinline__ float silu_f(float x) {
    return __fdividef(x, 1.f + __expf(-x));
}

__device__ __forceinline__ unsigned long long ffma2(unsigned long long a,
                                                    unsigned long long b,
                                                    unsigned long long c) {
    unsigned long long d;
    asm("fma.rn.f32x2 %0, %1, %2, %3;" : "=l"(d) : "l"(a), "l"(b), "l"(c));
    return d;
}

__device__ __forceinline__ unsigned long long pack2(float lo, float hi) {
    unsigned long long r;
    asm("mov.b64 %0, {%1, %2};" : "=l"(r) : "f"(lo), "f"(hi));
    return r;
}

__device__ __forceinline__ float2 unpack2(unsigned long long v) {
    float2 r;
    asm("mov.b64 {%0, %1}, %2;" : "=f"(r.x), "=f"(r.y) : "l"(v));
    return r;
}

__global__ __launch_bounds__(TPB2, 3)
void edge_kernel(const float* __restrict__ dist,
                 const int*   __restrict__ nbrs,
                 const float* __restrict__ W_dk,
                 const float* __restrict__ b_dk,
                 float*       __restrict__ out)
{
    __shared__ alignas(16) float ef_s[2][EPB][24];   // 20 RBF values, padded row
    __shared__ int2 idx_s[2][EPB];

    const int tid  = threadIdx.x;
    const int lane = tid & 31;
    const int warp = tid >> 5;           // == head
    const int c0   = warp * 64 + lane * 2;

    // Base pointers with the column offset folded in once
    const float* __restrict__ gQ = g_QK + c0;
    const float* __restrict__ gK = g_QK + HF + c0;

    // W_dk rows for cols c0 and c0+1 (each 20 floats, 80B => 16B aligned),
    // as r-packed f32x2 pairs: 10 pairs per column.
    const ulonglong2* wpA = (const ulonglong2*)(W_dk + (size_t)c0 * N_RBF);
    const ulonglong2* wpB = (const ulonglong2*)(W_dk + (size_t)(c0 + 1) * N_RBF);
    const ulonglong2 wa0 = wpA[0], wa1 = wpA[1], wa2 = wpA[2], wa3 = wpA[3], wa4 = wpA[4];
    const ulonglong2 wb0 = wpB[0], wb1 = wpB[1], wb2 = wpB[2], wb3 = wpB[3], wb4 = wpB[4];
    const unsigned long long aA0 = pack2(b_dk[c0], 0.f);
    const unsigned long long aB0 = pack2(b_dk[c0 + 1], 0.f);
    const unsigned long long zz  = pack2(0.f, 0.f);

    // stage-1 fill for group g into buffer buf
    auto fill = [&](int g, int buf) {
        const int e0 = g * EPB;
        #pragma unroll
        for (int v = tid; v < EPB * N_RBF; v += TPB2) {
            int el = v / N_RBF, r = v % N_RBF;
            float d   = dist[e0 + el];
            float t   = PI_F * d * (1.0f / CUTOFF);
            float env = (d < CUTOFF) ? 0.5f * (__cosf(t) + 1.f) : 0.f;
            ef_s[buf][el][r] = __sinf((float)(r + 1) * t) * __fdividef(env, d);
        }
        if (tid < EPB)
            idx_s[buf][tid] = ((const int2*)nbrs)[e0 + tid];
    };

    int g = blockIdx.x;
    fill(g, 0);
    int buf = 0;

    for (; g < NGROUPS; g += GRID2) {
        __syncthreads();                 // buf ready for everyone
        const int gn = g + GRID2;
        if (gn < NGROUPS) fill(gn, buf ^ 1);   // prefetch next group's RBF

        const int e0 = g * EPB;
        #pragma unroll 2
        for (int el = 0; el < EPB; el++) {
            int2 nn = idx_s[buf][el];
            float2 q = *(const float2*)(gQ + (size_t)nn.x * NCOLS);
            float2 k = *(const float2*)(gK + (size_t)nn.y * NCOLS);
            const ulonglong2* efp = (const ulonglong2*)&ef_s[buf][el][0];
            ulonglong2 e0v = efp[0], e1v = efp[1], e2v = efp[2], e3v = efp[3], e4v = efp[4];

            unsigned long long aA1 = aA0, aA2 = zz;   // column c0
            unsigned long long aB1 = aB0, aB2 = zz;   // column c0+1
            aA1 = ffma2(e0v.x, wa0.x, aA1);  aA2 = ffma2(e0v.y, wa0.y, aA2);
            aB1 = ffma2(e0v.x, wb0.x, aB1);  aB2 = ffma2(e0v.y, wb0.y, aB2);
            aA1 = ffma2(e1v.x, wa1.x, aA1);  aA2 = ffma2(e1v.y, wa1.y, aA2);
            aB1 = ffma2(e1v.x, wb1.x, aB1);  aB2 = ffma2(e1v.y, wb1.y, aB2);
            aA1 = ffma2(e2v.x, wa2.x, aA1);  aA2 = ffma2(e2v.y, wa2.y, aA2);
            aB1 = ffma2(e2v.x, wb2.x, aB1);  aB2 = ffma2(e2v.y, wb2.y, aB2);
            aA1 = ffma2(e3v.x, wa3.x, aA1);  aA2 = ffma2(e3v.y, wa3.y, aA2);
            aB1 = ffma2(e3v.x, wb3.x, aB1);  aB2 = ffma2(e3v.y, wb3.y, aB2);
            aA1 = ffma2(e4v.x, wa4.x, aA1);  aA2 = ffma2(e4v.y, wa4.y, aA2);
            aB1 = ffma2(e4v.x, wb4.x, aB1);  aB2 = ffma2(e4v.y, wb4.y, aB2);

            float2 fa1 = unpack2(aA1), fa2 = unpack2(aA2);
            float2 fb1 = unpack2(aB1), fb2 = unpack2(aB2);
            float sA = (fa1.x + fa1.y) + (fa2.x + fa2.y);
            float sB = (fb1.x + fb1.y) + (fb2.x + fb2.y);

            float p = q.x * k.x * silu_f(sA);
            p = fmaf(q.y * k.y, silu_f(sB), p);

            // full-warp butterfly: head sum
            p += __shfl_xor_sync(0xffffffffu, p, 16);
            p += __shfl_xor_sync(0xffffffffu, p, 8);
            p += __shfl_xor_sync(0xffffffffu, p, 4);
            p += __shfl_xor_sync(0xffffffffu, p, 2);
            p += __shfl_xor_sync(0xffffffffu, p, 1);
            if (lane == 0)
                out[(size_t)(e0 + el) * HEADS + warp] = silu_f(p);
        }
        buf ^= 1;
    }
}

// ---------------------------------------------------------------------------
extern "C" void kernel_launch(void* const* d_in, const int* in_sizes, int n_in,
                              void* d_out, int out_size)
{
    const float* dist = (const float*)d_in[0];
    const int*   nbrs = (const int*)  d_in[1];
    const float* x_i  = (const float*)d_in[2];
    const float* W_q  = (const float*)d_in[3];
    const float* b_q  = (const float*)d_in[4];
    const float* W_k  = (const float*)d_in[5];
    const float* b_k  = (const float*)d_in[6];
    const float* W_dk = (const float*)d_in[7];
    const float* b_dk = (const float*)d_in[8];
    float* out = (float*)d_out;

    dim3 g1((N_NODES + BM - 1) / BM, NCOLS / BN);   // 157 x 8
    qk_gemm_kernel<<<g1, 256>>>(x_i, W_q, b_q, W_k, b_k);

    edge_kernel<<<GRID2, TPB2>>>(dist, nbrs, W_dk, b_dk, out);
}

// round 7
// speedup vs baseline: 1.6300x; 1.1976x over previous
#include <cuda_runtime.h>
#include <math.h>

#define N_NODES 20000
#define N_EDGES 150000
#define FEAT    64
#define HEADS   8
#define N_RBF   20
#define HF      512          // HEADS*FEAT
#define NCOLS   1024         // Q(512) | K(512)
#define CUTOFF  5.0f
#define PI_F    3.14159265358979f

// Scratch: per-node Q and K projections, [node][ Q(0..511) | K(512..1023) ]
__device__ float g_QK[(size_t)N_NODES * NCOLS];

// ---------------------------------------------------------------------------
// Kernel 1: fused Q|K projection GEMM (unchanged).
// ---------------------------------------------------------------------------
#define BM 128
#define BN 128
#define BK 32
#define LDP 132   // padded leading dim for transposed tiles (conflict-free)

__global__ __launch_bounds__(256)
void qk_gemm_kernel(const float* __restrict__ x_i,
                    const float* __restrict__ W_q, const float* __restrict__ b_q,
                    const float* __restrict__ W_k, const float* __restrict__ b_k)
{
    __shared__ float A_t[BK][LDP];   // A_t[k][m]
    __shared__ float B_t[BK][LDP];   // B_t[k][n]

    const int tid  = threadIdx.x;
    const int row0 = blockIdx.x * BM;
    const int col0 = blockIdx.y * BN;

    const float* Bsrc;
    const float* bias_src;
    if (col0 < HF) { Bsrc = W_q + (size_t)col0 * FEAT;        bias_src = b_q + col0; }
    else           { Bsrc = W_k + (size_t)(col0 - HF) * FEAT; bias_src = b_k + (col0 - HF); }

    const int tx = tid & 15;     // 0..15 -> col group
    const int ty = tid >> 4;     // 0..15 -> row group

    float acc[8][8];
    #pragma unroll
    for (int i = 0; i < 8; i++)
        #pragma unroll
        for (int j = 0; j < 8; j++) acc[i][j] = 0.f;

    for (int kk = 0; kk < FEAT; kk += BK) {
        #pragma unroll
        for (int r = 0; r < 4; r++) {
            int f  = tid + 256 * r;      // 0..1023
            int ml = f >> 3;             // local row 0..127
            int kg = f & 7;              // float4 group within BK
            int m  = row0 + ml;
            float4 va = make_float4(0.f, 0.f, 0.f, 0.f);
            if (m < N_NODES)
                va = *(const float4*)(x_i + (size_t)m * FEAT + kk + kg * 4);
            A_t[kg * 4 + 0][ml] = va.x;
            A_t[kg * 4 + 1][ml] = va.y;
            A_t[kg * 4 + 2][ml] = va.z;
            A_t[kg * 4 + 3][ml] = va.w;
            float4 vb = *(const float4*)(Bsrc + (size_t)ml * FEAT + kk + kg * 4);
            B_t[kg * 4 + 0][ml] = vb.x;
            B_t[kg * 4 + 1][ml] = vb.y;
            B_t[kg * 4 + 2][ml] = vb.z;
            B_t[kg * 4 + 3][ml] = vb.w;
        }
        __syncthreads();

        #pragma unroll
        for (int k = 0; k < BK; k++) {
            float a[8], b[8];
            *(float4*)(a)     = *(const float4*)&A_t[k][ty * 8];
            *(float4*)(a + 4) = *(const float4*)&A_t[k][ty * 8 + 4];
            *(float4*)(b)     = *(const float4*)&B_t[k][tx * 8];
            *(float4*)(b + 4) = *(const float4*)&B_t[k][tx * 8 + 4];
            #pragma unroll
            for (int i = 0; i < 8; i++)
                #pragma unroll
                for (int j = 0; j < 8; j++)
                    acc[i][j] += a[i] * b[j];
        }
        __syncthreads();
    }

    float bias[8];
    #pragma unroll
    for (int j = 0; j < 8; j++) bias[j] = bias_src[tx * 8 + j];

    #pragma unroll
    for (int i = 0; i < 8; i++) {
        int m = row0 + ty * 8 + i;
        if (m < N_NODES) {
            float* dst = &g_QK[(size_t)m * NCOLS + col0 + tx * 8];
            float4 o0, o1;
            o0.x = acc[i][0] + bias[0]; o0.y = acc[i][1] + bias[1];
            o0.z = acc[i][2] + bias[2]; o0.w = acc[i][3] + bias[3];
            o1.x = acc[i][4] + bias[4]; o1.y = acc[i][5] + bias[5];
            o1.z = acc[i][6] + bias[6]; o1.w = acc[i][7] + bias[7];
            *(float4*)(dst)     = o0;
            *(float4*)(dst + 4) = o1;
        }
    }
}

// ---------------------------------------------------------------------------
// Kernel 2: fused edge kernel, 256 threads, warp == head, 2 cols/thread.
// Depth-2 q/k prefetch pipeline; 3-level octet butterfly + smem partials,
// finished once per 16-edge group (batched coalesced output stores).
// ---------------------------------------------------------------------------
#define EPB 16                    // edges per block iteration
#define NGROUPS (N_EDGES / EPB)   // 9375, exact
#define GRID2   444               // 148 SMs * 3 CTAs
#define TPB2    256

__device__ __forceinline__ float silu_f(float x) {
    return __fdividef(x, 1.f + __expf(-x));
}

__device__ __forceinline__ unsigned long long ffma2(unsigned long long a,
                                                    unsigned long long b,
                                                    unsigned long long c) {
    unsigned long long d;
    asm("fma.rn.f32x2 %0, %1, %2, %3;" : "=l"(d) : "l"(a), "l"(b), "l"(c));
    return d;
}

__device__ __forceinline__ unsigned long long pack2(float lo, float hi) {
    unsigned long long r;
    asm("mov.b64 %0, {%1, %2};" : "=l"(r) : "f"(lo), "f"(hi));
    return r;
}

__device__ __forceinline__ float2 unpack2(unsigned long long v) {
    float2 r;
    asm("mov.b64 {%0, %1}, %2;" : "=f"(r.x), "=f"(r.y) : "l"(v));
    return r;
}

__global__ __launch_bounds__(TPB2, 3)
void edge_kernel(const float* __restrict__ dist,
                 const int*   __restrict__ nbrs,
                 const float* __restrict__ W_dk,
                 const float* __restrict__ b_dk,
                 float*       __restrict__ out)
{
    __shared__ alignas(16) float ef_s[2][EPB][24];   // 20 RBF values, padded row
    __shared__ int2 idx_s[2][EPB];
    __shared__ alignas(16) float oct_s[HEADS][EPB][4];  // octet partials per warp

    const int tid  = threadIdx.x;
    const int lane = tid & 31;
    const int warp = tid >> 5;           // == head
    const int c0   = warp * 64 + lane * 2;

    // Base pointers with the column offset folded in once
    const float* __restrict__ gQ = g_QK + c0;
    const float* __restrict__ gK = g_QK + HF + c0;

    // W_dk rows for cols c0 and c0+1 (each 20 floats, 80B => 16B aligned),
    // as r-packed f32x2 pairs: 10 pairs per column.
    const ulonglong2* wpA = (const ulonglong2*)(W_dk + (size_t)c0 * N_RBF);
    const ulonglong2* wpB = (const ulonglong2*)(W_dk + (size_t)(c0 + 1) * N_RBF);
    const ulonglong2 wa0 = wpA[0], wa1 = wpA[1], wa2 = wpA[2], wa3 = wpA[3], wa4 = wpA[4];
    const ulonglong2 wb0 = wpB[0], wb1 = wpB[1], wb2 = wpB[2], wb3 = wpB[3], wb4 = wpB[4];
    const unsigned long long aA0 = pack2(b_dk[c0], 0.f);
    const unsigned long long aB0 = pack2(b_dk[c0 + 1], 0.f);
    const unsigned long long zz  = pack2(0.f, 0.f);

    // stage-1 fill for group g into buffer buf
    auto fill = [&](int g, int buf) {
        const int e0 = g * EPB;
        #pragma unroll
        for (int v = tid; v < EPB * N_RBF; v += TPB2) {
            int el = v / N_RBF, r = v % N_RBF;
            float d   = dist[e0 + el];
            float t   = PI_F * d * (1.0f / CUTOFF);
            float env = (d < CUTOFF) ? 0.5f * (__cosf(t) + 1.f) : 0.f;
            ef_s[buf][el][r] = __sinf((float)(r + 1) * t) * __fdividef(env, d);
        }
        if (tid < EPB)
            idx_s[buf][tid] = ((const int2*)nbrs)[e0 + tid];
    };

    int g = blockIdx.x;
    fill(g, 0);
    int buf = 0;

    for (; g < NGROUPS; g += GRID2) {
        __syncthreads();                 // buf ready for everyone
        const int gn = g + GRID2;
        if (gn < NGROUPS) fill(gn, buf ^ 1);   // prefetch next group's RBF

        const int e0 = g * EPB;

        // --- depth-2 pipeline: q/k for edge el+1 loads while edge el computes
        int2 nn = idx_s[buf][0];
        float2 q = *(const float2*)(gQ + (size_t)nn.x * NCOLS);
        float2 k = *(const float2*)(gK + (size_t)nn.y * NCOLS);

        #pragma unroll 4
        for (int el = 0; el < EPB; el++) {
            float2 qc = q, kc = k;
            if (el + 1 < EPB) {
                int2 nn1 = idx_s[buf][el + 1];
                q = *(const float2*)(gQ + (size_t)nn1.x * NCOLS);
                k = *(const float2*)(gK + (size_t)nn1.y * NCOLS);
            }

            const ulonglong2* efp = (const ulonglong2*)&ef_s[buf][el][0];
            ulonglong2 e0v = efp[0], e1v = efp[1], e2v = efp[2], e3v = efp[3], e4v = efp[4];

            unsigned long long aA1 = aA0, aA2 = zz;   // column c0
            unsigned long long aB1 = aB0, aB2 = zz;   // column c0+1
            aA1 = ffma2(e0v.x, wa0.x, aA1);  aA2 = ffma2(e0v.y, wa0.y, aA2);
            aB1 = ffma2(e0v.x, wb0.x, aB1);  aB2 = ffma2(e0v.y, wb0.y, aB2);
            aA1 = ffma2(e1v.x, wa1.x, aA1);  aA2 = ffma2(e1v.y, wa1.y, aA2);
            aB1 = ffma2(e1v.x, wb1.x, aB1);  aB2 = ffma2(e1v.y, wb1.y, aB2);
            aA1 = ffma2(e2v.x, wa2.x, aA1);  aA2 = ffma2(e2v.y, wa2.y, aA2);
            aB1 = ffma2(e2v.x, wb2.x, aB1);  aB2 = ffma2(e2v.y, wb2.y, aB2);
            aA1 = ffma2(e3v.x, wa3.x, aA1);  aA2 = ffma2(e3v.y, wa3.y, aA2);
            aB1 = ffma2(e3v.x, wb3.x, aB1);  aB2 = ffma2(e3v.y, wb3.y, aB2);
            aA1 = ffma2(e4v.x, wa4.x, aA1);  aA2 = ffma2(e4v.y, wa4.y, aA2);
            aB1 = ffma2(e4v.x, wb4.x, aB1);  aB2 = ffma2(e4v.y, wb4.y, aB2);

            float2 fa1 = unpack2(aA1), fa2 = unpack2(aA2);
            float2 fb1 = unpack2(aB1), fb2 = unpack2(aB2);
            float sA = (fa1.x + fa1.y) + (fa2.x + fa2.y);
            float sB = (fb1.x + fb1.y) + (fb2.x + fb2.y);

            float p = qc.x * kc.x * silu_f(sA);
            p = fmaf(qc.y * kc.y, silu_f(sB), p);

            // 3-level octet butterfly; 4 partials per edge land in smem
            p += __shfl_xor_sync(0xffffffffu, p, 4);
            p += __shfl_xor_sync(0xffffffffu, p, 2);
            p += __shfl_xor_sync(0xffffffffu, p, 1);
            if ((lane & 7) == 0) oct_s[warp][el][lane >> 3] = p;
        }
        __syncwarp();

        // --- finish: lanes 0..15 each close one edge (batched, coalesced)
        if (lane < EPB) {
            const float4 pv = *(const float4*)&oct_s[warp][lane][0];
            float s = (pv.x + pv.y) + (pv.z + pv.w);
            out[(size_t)(e0 + lane) * HEADS + warp] = silu_f(s);
        }
        __syncwarp();
        buf ^= 1;
    }
}

// ---------------------------------------------------------------------------
extern "C" void kernel_launch(void* const* d_in, const int* in_sizes, int n_in,
                              void* d_out, int out_size)
{
    const float* dist = (const float*)d_in[0];
    const int*   nbrs = (const int*)  d_in[1];
    const float* x_i  = (const float*)d_in[2];
    const float* W_q  = (const float*)d_in[3];
    const float* b_q  = (const float*)d_in[4];
    const float* W_k  = (const float*)d_in[5];
    const float* b_k  = (const float*)d_in[6];
    const float* W_dk = (const float*)d_in[7];
    const float* b_dk = (const float*)d_in[8];
    float* out = (float*)d_out;

    dim3 g1((N_NODES + BM - 1) / BM, NCOLS / BN);   // 157 x 8
    qk_gemm_kernel<<<g1, 256>>>(x_i, W_q, b_q, W_k, b_k);

    edge_kernel<<<GRID2, TPB2>>>(dist, nbrs, W_dk, b_dk, out);
}

// round 8
// speedup vs baseline: 1.6568x; 1.0164x over previous
#include <cuda_runtime.h>
#include <math.h>

#define N_NODES 20000
#define N_EDGES 150000
#define FEAT    64
#define HEADS   8
#define N_RBF   20
#define HF      512          // HEADS*FEAT
#define NCOLS   1024         // Q(512) | K(512)
#define CUTOFF  5.0f
#define PI_F    3.14159265358979f

// Scratch: per-node Q and K projections, [node][ Q(0..511) | K(512..1023) ]
__device__ float g_QK[(size_t)N_NODES * NCOLS];

// ---------------------------------------------------------------------------
// Packed f32x2 helpers (Blackwell FFMA2 — only reachable via PTX fma.rn.f32x2)
// ---------------------------------------------------------------------------
__device__ __forceinline__ unsigned long long ffma2(unsigned long long a,
                                                    unsigned long long b,
                                                    unsigned long long c) {
    unsigned long long d;
    asm("fma.rn.f32x2 %0, %1, %2, %3;" : "=l"(d) : "l"(a), "l"(b), "l"(c));
    return d;
}

__device__ __forceinline__ unsigned long long pack2(float lo, float hi) {
    unsigned long long r;
    asm("mov.b64 %0, {%1, %2};" : "=l"(r) : "f"(lo), "f"(hi));
    return r;
}

__device__ __forceinline__ float2 unpack2(unsigned long long v) {
    float2 r;
    asm("mov.b64 {%0, %1}, %2;" : "=f"(r.x), "=f"(r.y) : "l"(v));
    return r;
}

// ---------------------------------------------------------------------------
// Kernel 1: fused Q|K projection GEMM, FFMA2 microtile.
// C[n, c] = sum_f x_i[n,f] * W[c,f] + b[c],  W = [W_q ; W_k] rows
// BM=128, BN=128, BK=32, 256 threads, 8x8 microtile (acc packed along j).
// ---------------------------------------------------------------------------
#define BM 128
#define BN 128
#define BK 32
#define LDP 132   // padded leading dim for transposed tiles (conflict-free)

__global__ __launch_bounds__(256)
void qk_gemm_kernel(const float* __restrict__ x_i,
                    const float* __restrict__ W_q, const float* __restrict__ b_q,
                    const float* __restrict__ W_k, const float* __restrict__ b_k)
{
    __shared__ float A_t[BK][LDP];   // A_t[k][m]
    __shared__ float B_t[BK][LDP];   // B_t[k][n]

    const int tid  = threadIdx.x;
    const int row0 = blockIdx.x * BM;
    const int col0 = blockIdx.y * BN;

    const float* Bsrc;
    const float* bias_src;
    if (col0 < HF) { Bsrc = W_q + (size_t)col0 * FEAT;        bias_src = b_q + col0; }
    else           { Bsrc = W_k + (size_t)(col0 - HF) * FEAT; bias_src = b_k + (col0 - HF); }

    const int tx = tid & 15;     // 0..15 -> col group
    const int ty = tid >> 4;     // 0..15 -> row group

    // acc2[i][j2] = (acc[i][2*j2], acc[i][2*j2+1]) packed
    unsigned long long acc2[8][4];
    const unsigned long long zz = pack2(0.f, 0.f);
    #pragma unroll
    for (int i = 0; i < 8; i++)
        #pragma unroll
        for (int j = 0; j < 4; j++) acc2[i][j] = zz;

    for (int kk = 0; kk < FEAT; kk += BK) {
        // Fill tiles: 128 rows x 32 k = 1024 float4 total, 4 per thread.
        #pragma unroll
        for (int r = 0; r < 4; r++) {
            int f  = tid + 256 * r;      // 0..1023
            int ml = f >> 3;             // local row 0..127
            int kg = f & 7;              // float4 group within BK
            int m  = row0 + ml;
            float4 va = make_float4(0.f, 0.f, 0.f, 0.f);
            if (m < N_NODES)
                va = *(const float4*)(x_i + (size_t)m * FEAT + kk + kg * 4);
            A_t[kg * 4 + 0][ml] = va.x;
            A_t[kg * 4 + 1][ml] = va.y;
            A_t[kg * 4 + 2][ml] = va.z;
            A_t[kg * 4 + 3][ml] = va.w;
            float4 vb = *(const float4*)(Bsrc + (size_t)ml * FEAT + kk + kg * 4);
            B_t[kg * 4 + 0][ml] = vb.x;
            B_t[kg * 4 + 1][ml] = vb.y;
            B_t[kg * 4 + 2][ml] = vb.z;
            B_t[kg * 4 + 3][ml] = vb.w;
        }
        __syncthreads();

        #pragma unroll
        for (int k = 0; k < BK; k++) {
            float a[8];
            *(float4*)(a)     = *(const float4*)&A_t[k][ty * 8];
            *(float4*)(a + 4) = *(const float4*)&A_t[k][ty * 8 + 4];
            // B as pre-packed 64-bit pairs straight out of shared (32B-aligned)
            ulonglong2 bv0 = *(const ulonglong2*)&B_t[k][tx * 8];
            ulonglong2 bv1 = *(const ulonglong2*)&B_t[k][tx * 8 + 4];
            unsigned long long bb[4] = {bv0.x, bv0.y, bv1.x, bv1.y};
            #pragma unroll
            for (int i = 0; i < 8; i++) {
                const unsigned long long ad = pack2(a[i], a[i]);
                #pragma unroll
                for (int j = 0; j < 4; j++)
                    acc2[i][j] = ffma2(bb[j], ad, acc2[i][j]);
            }
        }
        __syncthreads();
    }

    float bias[8];
    #pragma unroll
    for (int j = 0; j < 8; j++) bias[j] = bias_src[tx * 8 + j];

    #pragma unroll
    for (int i = 0; i < 8; i++) {
        int m = row0 + ty * 8 + i;
        if (m < N_NODES) {
            float* dst = &g_QK[(size_t)m * NCOLS + col0 + tx * 8];
            float2 c0 = unpack2(acc2[i][0]), c1 = unpack2(acc2[i][1]);
            float2 c2 = unpack2(acc2[i][2]), c3 = unpack2(acc2[i][3]);
            float4 o0, o1;
            o0.x = c0.x + bias[0]; o0.y = c0.y + bias[1];
            o0.z = c1.x + bias[2]; o0.w = c1.y + bias[3];
            o1.x = c2.x + bias[4]; o1.y = c2.y + bias[5];
            o1.z = c3.x + bias[6]; o1.w = c3.y + bias[7];
            *(float4*)(dst)     = o0;
            *(float4*)(dst + 4) = o1;
        }
    }
}

// ---------------------------------------------------------------------------
// Kernel 2: fused edge kernel, 256 threads, warp == head, 2 cols/thread.
// Depth-3 q/k prefetch pipeline (fully unrolled 16-edge loop); 3-level octet
// butterfly + smem partials finished once per group (batched stores).
// ---------------------------------------------------------------------------
#define EPB 16                    // edges per block iteration
#define NGROUPS (N_EDGES / EPB)   // 9375, exact
#define GRID2   444               // 148 SMs * 3 CTAs
#define TPB2    256

__device__ __forceinline__ float silu_f(float x) {
    return __fdividef(x, 1.f + __expf(-x));
}

__global__ __launch_bounds__(TPB2, 3)
void edge_kernel(const float* __restrict__ dist,
                 const int*   __restrict__ nbrs,
                 const float* __restrict__ W_dk,
                 const float* __restrict__ b_dk,
                 float*       __restrict__ out)
{
    __shared__ alignas(16) float ef_s[2][EPB][24];   // 20 RBF values, padded row
    __shared__ int2 idx_s[2][EPB];
    __shared__ alignas(16) float oct_s[HEADS][EPB][4];  // octet partials per warp

    const int tid  = threadIdx.x;
    const int lane = tid & 31;
    const int warp = tid >> 5;           // == head
    const int c0   = warp * 64 + lane * 2;

    // Base pointers with the column offset folded in once
    const float* __restrict__ gQ = g_QK + c0;
    const float* __restrict__ gK = g_QK + HF + c0;

    // W_dk rows for cols c0 and c0+1 (each 20 floats, 80B => 16B aligned),
    // as r-packed f32x2 pairs: 10 pairs per column.
    const ulonglong2* wpA = (const ulonglong2*)(W_dk + (size_t)c0 * N_RBF);
    const ulonglong2* wpB = (const ulonglong2*)(W_dk + (size_t)(c0 + 1) * N_RBF);
    const ulonglong2 wa0 = wpA[0], wa1 = wpA[1], wa2 = wpA[2], wa3 = wpA[3], wa4 = wpA[4];
    const ulonglong2 wb0 = wpB[0], wb1 = wpB[1], wb2 = wpB[2], wb3 = wpB[3], wb4 = wpB[4];
    const unsigned long long aA0 = pack2(b_dk[c0], 0.f);
    const unsigned long long aB0 = pack2(b_dk[c0 + 1], 0.f);
    const unsigned long long zz  = pack2(0.f, 0.f);

    // stage-1 fill for group g into buffer buf
    auto fill = [&](int g, int buf) {
        const int e0 = g * EPB;
        #pragma unroll
        for (int v = tid; v < EPB * N_RBF; v += TPB2) {
            int el = v / N_RBF, r = v % N_RBF;
            float d   = dist[e0 + el];
            float t   = PI_F * d * (1.0f / CUTOFF);
            float env = (d < CUTOFF) ? 0.5f * (__cosf(t) + 1.f) : 0.f;
            ef_s[buf][el][r] = __sinf((float)(r + 1) * t) * __fdividef(env, d);
        }
        if (tid < EPB)
            idx_s[buf][tid] = ((const int2*)nbrs)[e0 + tid];
    };

    int g = blockIdx.x;
    fill(g, 0);
    int buf = 0;

    for (; g < NGROUPS; g += GRID2) {
        __syncthreads();                 // buf ready for everyone
        const int gn = g + GRID2;
        if (gn < NGROUPS) fill(gn, buf ^ 1);   // prefetch next group's RBF

        const int e0 = g * EPB;

        // --- depth-3 q/k prefetch pipeline
        float2 q0, k0, q1, k1, q2, k2;
        {
            int2 a = idx_s[buf][0];
            q0 = *(const float2*)(gQ + (size_t)a.x * NCOLS);
            k0 = *(const float2*)(gK + (size_t)a.y * NCOLS);
            int2 b = idx_s[buf][1];
            q1 = *(const float2*)(gQ + (size_t)b.x * NCOLS);
            k1 = *(const float2*)(gK + (size_t)b.y * NCOLS);
            int2 c = idx_s[buf][2];
            q2 = *(const float2*)(gQ + (size_t)c.x * NCOLS);
            k2 = *(const float2*)(gK + (size_t)c.y * NCOLS);
        }

        #pragma unroll
        for (int el = 0; el < EPB; el++) {
            float2 qc = q0, kc = k0;
            q0 = q1; k0 = k1;
            q1 = q2; k1 = k2;
            if (el + 3 < EPB) {
                int2 nn3 = idx_s[buf][el + 3];
                q2 = *(const float2*)(gQ + (size_t)nn3.x * NCOLS);
                k2 = *(const float2*)(gK + (size_t)nn3.y * NCOLS);
            }

            const ulonglong2* efp = (const ulonglong2*)&ef_s[buf][el][0];
            ulonglong2 e0v = efp[0], e1v = efp[1], e2v = efp[2], e3v = efp[3], e4v = efp[4];

            unsigned long long aA1 = aA0, aA2 = zz;   // column c0
            unsigned long long aB1 = aB0, aB2 = zz;   // column c0+1
            aA1 = ffma2(e0v.x, wa0.x, aA1);  aA2 = ffma2(e0v.y, wa0.y, aA2);
            aB1 = ffma2(e0v.x, wb0.x, aB1);  aB2 = ffma2(e0v.y, wb0.y, aB2);
            aA1 = ffma2(e1v.x, wa1.x, aA1);  aA2 = ffma2(e1v.y, wa1.y, aA2);
            aB1 = ffma2(e1v.x, wb1.x, aB1);  aB2 = ffma2(e1v.y, wb1.y, aB2);
            aA1 = ffma2(e2v.x, wa2.x, aA1);  aA2 = ffma2(e2v.y, wa2.y, aA2);
            aB1 = ffma2(e2v.x, wb2.x, aB1);  aB2 = ffma2(e2v.y, wb2.y, aB2);
            aA1 = ffma2(e3v.x, wa3.x, aA1);  aA2 = ffma2(e3v.y, wa3.y, aA2);
            aB1 = ffma2(e3v.x, wb3.x, aB1);  aB2 = ffma2(e3v.y, wb3.y, aB2);
            aA1 = ffma2(e4v.x, wa4.x, aA1);  aA2 = ffma2(e4v.y, wa4.y, aA2);
            aB1 = ffma2(e4v.x, wb4.x, aB1);  aB2 = ffma2(e4v.y, wb4.y, aB2);

            float2 fa1 = unpack2(aA1), fa2 = unpack2(aA2);
            float2 fb1 = unpack2(aB1), fb2 = unpack2(aB2);
            float sA = (fa1.x + fa1.y) + (fa2.x + fa2.y);
            float sB = (fb1.x + fb1.y) + (fb2.x + fb2.y);

            float p = qc.x * kc.x * silu_f(sA);
            p = fmaf(qc.y * kc.y, silu_f(sB), p);

            // 3-level octet butterfly; 4 partials per edge land in smem
            p += __shfl_xor_sync(0xffffffffu, p, 4);
            p += __shfl_xor_sync(0xffffffffu, p, 2);
            p += __shfl_xor_sync(0xffffffffu, p, 1);
            if ((lane & 7) == 0) oct_s[warp][el][lane >> 3] = p;
        }
        __syncwarp();

        // --- finish: lanes 0..15 each close one edge (batched, coalesced)
        if (lane < EPB) {
            const float4 pv = *(const float4*)&oct_s[warp][lane][0];
            float s = (pv.x + pv.y) + (pv.z + pv.w);
            out[(size_t)(e0 + lane) * HEADS + warp] = silu_f(s);
        }
        __syncwarp();
        buf ^= 1;
    }
}

// ---------------------------------------------------------------------------
extern "C" void kernel_launch(void* const* d_in, const int* in_sizes, int n_in,
                              void* d_out, int out_size)
{
    const float* dist = (const float*)d_in[0];
    const int*   nbrs = (const int*)  d_in[1];
    const float* x_i  = (const float*)d_in[2];
    const float* W_q  = (const float*)d_in[3];
    const float* b_q  = (const float*)d_in[4];
    const float* W_k  = (const float*)d_in[5];
    const float* b_k  = (const float*)d_in[6];
    const float* W_dk = (const float*)d_in[7];
    const float* b_dk = (const float*)d_in[8];
    float* out = (float*)d_out;

    dim3 g1((N_NODES + BM - 1) / BM, NCOLS / BN);   // 157 x 8
    qk_gemm_kernel<<<g1, 256>>>(x_i, W_q, b_q, W_k, b_k);

    edge_kernel<<<GRID2, TPB2>>>(dist, nbrs, W_dk, b_dk, out);
}